// round 2
// baseline (speedup 1.0000x reference)
#include <cuda_runtime.h>
#include <math.h>

#define N_NODES 50000
#define N_EDGES 800000
#define IN_DIM  256
#define OUT_DIM 128
#define HID     64
#define NCLS    3

// ---------------- device scratch (no allocations allowed) ----------------
__device__ float    g_Wh[(size_t)N_NODES * OUT_DIM];
__device__ float    g_scores[N_EDGES];
__device__ float    g_ssrc[N_NODES];
__device__ float    g_stgt[N_NODES];
__device__ unsigned g_maxenc;
__device__ float    g_sum;
__device__ unsigned g_or32;   // 0 => edge_index is int64, nonzero => int32

// monotonic float<->uint encoding for atomicMax over signed floats
__device__ __forceinline__ unsigned encf(float f) {
    unsigned u = __float_as_uint(f);
    return (u & 0x80000000u) ? ~u : (u | 0x80000000u);
}
__device__ __forceinline__ float decf(unsigned e) {
    unsigned u = (e & 0x80000000u) ? (e & 0x7fffffffu) : ~e;
    return __uint_as_float(u);
}

__device__ __forceinline__ int load_index(const void* p, long i, bool is64) {
    if (is64) return (int)((const long long*)p)[i];
    return ((const int*)p)[i];
}

// ---------------- kernels ----------------

// zero x_new region of output, init reduction scalars, AND detect index dtype.
// Grid: 6250 blocks x 256. First 1.6M threads zero; first 800k also scan.
__global__ void __launch_bounds__(256) k_init(float* __restrict__ out,
                                              const void* __restrict__ eidx) {
    long i = (long)blockIdx.x * blockDim.x + threadIdx.x;
    ((float4*)out)[i] = make_float4(0.f, 0.f, 0.f, 0.f);
    if (i == 0) { g_maxenc = 0u; g_sum = 0.f; }
    // dtype detection: OR of odd 32-bit words in first N_EDGES word-pairs.
    // If buffer is int64 (values < 2^31, positive), all odd words are 0.
    if (i < N_EDGES) {
        unsigned v = ((const unsigned*)eidx)[2 * i + 1];
        if (__any_sync(0xffffffffu, v != 0u) && ((threadIdx.x & 31) == 0))
            atomicOr(&g_or32, 1u);
    }
}

// Wh = x @ W  (M=50000, K=256, N=128), fused s_src/s_tgt epilogue.
// Tile 64x128, TK=32, 256 threads, each thread 4 rows x 8 cols.
__global__ void __launch_bounds__(256) k_gemm(const float* __restrict__ x,
                                              const float* __restrict__ W,
                                              const float* __restrict__ a) {
    __shared__ float xs[32][64];        // transposed: xs[k][row]
    __shared__ float ws[32][OUT_DIM];   // ws[k][col]
    int tid = threadIdx.x;
    int tx = tid & 15;                  // col group (8 cols)
    int ty = tid >> 4;                  // row group (4 rows)
    int row0 = blockIdx.x * 64;

    float acc[4][8];
#pragma unroll
    for (int i = 0; i < 4; i++)
#pragma unroll
        for (int j = 0; j < 8; j++) acc[i][j] = 0.f;

    for (int k0 = 0; k0 < IN_DIM; k0 += 32) {
        // x tile: 64 rows x 32 k = 512 float4 loads
#pragma unroll
        for (int r = 0; r < 2; r++) {
            int m = tid + 256 * r;          // 0..511
            int rr = m >> 3;                // row 0..63
            int c4 = m & 7;                 // float4 within k-chunk
            int grow = row0 + rr;
            float4 v = make_float4(0.f, 0.f, 0.f, 0.f);
            if (grow < N_NODES)
                v = *(const float4*)(x + (long)grow * IN_DIM + k0 + c4 * 4);
            xs[c4 * 4 + 0][rr] = v.x;
            xs[c4 * 4 + 1][rr] = v.y;
            xs[c4 * 4 + 2][rr] = v.z;
            xs[c4 * 4 + 3][rr] = v.w;
        }
        // W tile: 32 x 128 = 1024 float4 loads
#pragma unroll
        for (int r = 0; r < 4; r++) {
            int m = tid + 256 * r;          // 0..1023
            int kk = m >> 5;
            int c4 = m & 31;
            *(float4*)&ws[kk][c4 * 4] =
                *(const float4*)(W + (long)(k0 + kk) * OUT_DIM + c4 * 4);
        }
        __syncthreads();
#pragma unroll
        for (int kk = 0; kk < 32; kk++) {
            float4 xv = *(float4*)&xs[kk][ty * 4];
            float4 w0 = *(float4*)&ws[kk][tx * 8];
            float4 w1 = *(float4*)&ws[kk][tx * 8 + 4];
            float xa[4] = {xv.x, xv.y, xv.z, xv.w};
            float wa[8] = {w0.x, w0.y, w0.z, w0.w, w1.x, w1.y, w1.z, w1.w};
#pragma unroll
            for (int i = 0; i < 4; i++)
#pragma unroll
                for (int j = 0; j < 8; j++) acc[i][j] += xa[i] * wa[j];
        }
        __syncthreads();
    }

    // epilogue: store Wh, fused attention projections s_src / s_tgt
    float a1[8], a2[8];
#pragma unroll
    for (int j = 0; j < 8; j++) {
        a1[j] = a[tx * 8 + j];
        a2[j] = a[OUT_DIM + tx * 8 + j];
    }
#pragma unroll
    for (int i = 0; i < 4; i++) {
        int grow = row0 + ty * 4 + i;
        float p1 = 0.f, p2 = 0.f;
#pragma unroll
        for (int j = 0; j < 8; j++) {
            p1 += acc[i][j] * a1[j];
            p2 += acc[i][j] * a2[j];
        }
        // reduce across the 16 tx lanes (lane bits 0..3)
#pragma unroll
        for (int o = 1; o < 16; o <<= 1) {
            p1 += __shfl_xor_sync(0xffffffffu, p1, o);
            p2 += __shfl_xor_sync(0xffffffffu, p2, o);
        }
        if (grow < N_NODES) {
            *(float4*)(g_Wh + (long)grow * OUT_DIM + tx * 8) =
                make_float4(acc[i][0], acc[i][1], acc[i][2], acc[i][3]);
            *(float4*)(g_Wh + (long)grow * OUT_DIM + tx * 8 + 4) =
                make_float4(acc[i][4], acc[i][5], acc[i][6], acc[i][7]);
            if (tx == 0) { g_ssrc[grow] = p1; g_stgt[grow] = p2; }
        }
    }
}

// scores + global max (block-reduced, one atomic per block)
__global__ void __launch_bounds__(256) k_score(const void* __restrict__ eidx) {
    int e = blockIdx.x * blockDim.x + threadIdx.x;   // exact grid
    bool is64 = (g_or32 == 0u);
    int s = load_index(eidx, e, is64);
    int t = load_index(eidx, (long)N_EDGES + e, is64);
    float sc = __ldg(g_ssrc + s) + __ldg(g_stgt + t);
    sc = sc > 0.f ? sc : 0.2f * sc;                  // leaky_relu 0.2
    g_scores[e] = sc;

    float m = sc;
#pragma unroll
    for (int o = 16; o > 0; o >>= 1) m = fmaxf(m, __shfl_xor_sync(0xffffffffu, m, o));
    __shared__ float red[8];
    int wid = threadIdx.x >> 5;
    if ((threadIdx.x & 31) == 0) red[wid] = m;
    __syncthreads();
    if (threadIdx.x == 0) {
        float bm = red[0];
#pragma unroll
        for (int i = 1; i < 8; i++) bm = fmaxf(bm, red[i]);
        atomicMax(&g_maxenc, encf(bm));
    }
}

// sum of exp(score - max) (block-reduced, one atomic per block)
__global__ void __launch_bounds__(256) k_sumexp() {
    int e = blockIdx.x * blockDim.x + threadIdx.x;   // exact grid
    float gmax = decf(g_maxenc);
    float z = expf(g_scores[e] - gmax);
#pragma unroll
    for (int o = 16; o > 0; o >>= 1) z += __shfl_xor_sync(0xffffffffu, z, o);
    __shared__ float red[8];
    int wid = threadIdx.x >> 5;
    if ((threadIdx.x & 31) == 0) red[wid] = z;
    __syncthreads();
    if (threadIdx.x == 0) {
        float bs = 0.f;
#pragma unroll
        for (int i = 0; i < 8; i++) bs += red[i];
        atomicAdd(&g_sum, bs);
    }
}

// scatter: x_new[tgt] += alpha * Wh[src].  One warp per edge, float4 RED.
__global__ void __launch_bounds__(256) k_scatter(const void* __restrict__ eidx,
                                                 float* __restrict__ xnew) {
    long w = ((long)blockIdx.x * 256 + threadIdx.x) >> 5;   // edge id, exact grid
    int lane = threadIdx.x & 31;
    bool is64 = (g_or32 == 0u);
    float gmax = decf(g_maxenc);
    float inv = 1.f / g_sum;
    int s = load_index(eidx, w, is64);
    int t = load_index(eidx, (long)N_EDGES + w, is64);
    float alpha = expf(__ldcs(g_scores + w) - gmax) * inv;
    float4 v = *(const float4*)(g_Wh + (long)s * OUT_DIM + lane * 4);
    v.x *= alpha; v.y *= alpha; v.z *= alpha; v.w *= alpha;
#if __CUDA_ARCH__ >= 900
    atomicAdd((float4*)(xnew + (long)t * OUT_DIM) + lane, v);
#else
    float* p = xnew + (long)t * OUT_DIM + lane * 4;
    atomicAdd(p + 0, v.x); atomicAdd(p + 1, v.y);
    atomicAdd(p + 2, v.z); atomicAdd(p + 3, v.w);
#endif
}

// MLP head: h = relu(x_new@W1+b1); evidence = softplus(h@W2+b2)+1
// 64 threads / block, 16 nodes / block (3125 blocks, exact).
__global__ void __launch_bounds__(64) k_mlp(const float* __restrict__ xnew,
                                            const float* __restrict__ W1,
                                            const float* __restrict__ b1,
                                            const float* __restrict__ W2,
                                            const float* __restrict__ b2,
                                            float* __restrict__ ev) {
    __shared__ float W1s[OUT_DIM * HID];   // 32 KB, [k][j]
    __shared__ float xs[OUT_DIM][16];      // [k][node]
    __shared__ float hs[16 * 65];          // padded to kill bank conflicts
    __shared__ float W2s[HID * NCLS];
    __shared__ float b2s[NCLS];

    int tid = threadIdx.x;                 // 0..63 (= hidden unit j)
    for (int i = tid; i < OUT_DIM * HID / 4; i += 64)
        ((float4*)W1s)[i] = ((const float4*)W1)[i];
    for (int i = tid; i < HID * NCLS; i += 64) W2s[i] = W2[i];
    if (tid < NCLS) b2s[tid] = b2[tid];
    float bb = b1[tid];

    int n0 = blockIdx.x * 16;
    // load 16 node rows, transposed into xs[k][n]
    for (int i = tid; i < 512; i += 64) {
        int c4 = i >> 4;                   // 0..31 (k float4 chunk)
        int n  = i & 15;                   // node 0..15
        float4 v = *(const float4*)(xnew + (long)(n0 + n) * OUT_DIM + c4 * 4);
        xs[c4 * 4 + 0][n] = v.x;
        xs[c4 * 4 + 1][n] = v.y;
        xs[c4 * 4 + 2][n] = v.z;
        xs[c4 * 4 + 3][n] = v.w;
    }
    __syncthreads();

    float acc[16];
#pragma unroll
    for (int n = 0; n < 16; n++) acc[n] = bb;
    for (int k = 0; k < OUT_DIM; k++) {
        float wv = W1s[k * HID + tid];
        float4 x0 = *(float4*)&xs[k][0];
        float4 x1 = *(float4*)&xs[k][4];
        float4 x2 = *(float4*)&xs[k][8];
        float4 x3 = *(float4*)&xs[k][12];
        acc[0]  += wv * x0.x; acc[1]  += wv * x0.y; acc[2]  += wv * x0.z; acc[3]  += wv * x0.w;
        acc[4]  += wv * x1.x; acc[5]  += wv * x1.y; acc[6]  += wv * x1.z; acc[7]  += wv * x1.w;
        acc[8]  += wv * x2.x; acc[9]  += wv * x2.y; acc[10] += wv * x2.z; acc[11] += wv * x2.w;
        acc[12] += wv * x3.x; acc[13] += wv * x3.y; acc[14] += wv * x3.z; acc[15] += wv * x3.w;
    }
#pragma unroll
    for (int n = 0; n < 16; n++) hs[n * 65 + tid] = fmaxf(acc[n], 0.f);
    __syncthreads();

    if (tid < 16 * NCLS) {                 // 48 threads: (node, class)
        int n = tid / NCLS, j = tid % NCLS;
        float z = b2s[j];
        for (int k = 0; k < HID; k++) z += hs[n * 65 + k] * W2s[k * NCLS + j];
        float sp = (z > 20.f) ? z : log1pf(expf(z));
        ev[(long)(n0 + n) * NCLS + j] = sp + 1.f;
    }
}

// ---------------- launch ----------------
extern "C" void kernel_launch(void* const* d_in, const int* in_sizes, int n_in,
                              void* d_out, int out_size) {
    const float* x  = (const float*)d_in[0];
    const void*  ei = d_in[1];
    const float* W  = (const float*)d_in[2];
    const float* a  = (const float*)d_in[3];
    const float* W1 = (const float*)d_in[4];
    const float* b1 = (const float*)d_in[5];
    const float* W2 = (const float*)d_in[6];
    const float* b2 = (const float*)d_in[7];
    float* out = (float*)d_out;
    float* ev  = out + (long)N_NODES * OUT_DIM;

    k_init   <<<(N_NODES * OUT_DIM / 4) / 256, 256>>>(out, ei); // 6250 blocks
    k_gemm   <<<(N_NODES + 63) / 64, 256>>>(x, W, a);           // 782
    k_score  <<<N_EDGES / 256, 256>>>(ei);                      // 3125
    k_sumexp <<<N_EDGES / 256, 256>>>();                        // 3125
    k_scatter<<<N_EDGES * 32 / 256, 256>>>(ei, out);            // 100000
    k_mlp    <<<N_NODES / 16, 64>>>(out, W1, b1, W2, b2, ev);   // 3125
}

// round 9
// speedup vs baseline: 1.1672x; 1.1672x over previous
#include <cuda_runtime.h>
#include <math.h>

#define N_NODES 50000
#define N_EDGES 800000
#define IN_DIM  256
#define OUT_DIM 128
#define HID     64
#define NCLS    3
#define NB_SCAN 196                 // ceil(50000/256)

// ---------------- device scratch (no allocations allowed) ----------------
__device__ float    g_Wh[(size_t)N_NODES * OUT_DIM];
__device__ float    g_scores[N_EDGES];
__device__ float    g_ssrc[N_NODES];
__device__ float    g_stgt[N_NODES];
__device__ int      g_src32[N_EDGES];
__device__ int      g_tgt32[N_EDGES];
__device__ int      g_deg[N_NODES];
__device__ int      g_off[N_NODES];
__device__ int      g_cursor[N_NODES];
__device__ int      g_scanv[N_NODES];
__device__ int      g_bsum[NB_SCAN];
__device__ int      g_boff[NB_SCAN];
__device__ int      g_csrc[N_EDGES];   // CSR: src per slot
__device__ float    g_cz[N_EDGES];     // CSR: exp(score-max) per slot
__device__ unsigned g_maxenc;
__device__ float    g_sum;
__device__ unsigned g_or32;   // 0 => edge_index is int64, nonzero => int32

// monotonic float<->uint encoding for atomicMax over signed floats
__device__ __forceinline__ unsigned encf(float f) {
    unsigned u = __float_as_uint(f);
    return (u & 0x80000000u) ? ~u : (u | 0x80000000u);
}
__device__ __forceinline__ float decf(unsigned e) {
    unsigned u = (e & 0x80000000u) ? (e & 0x7fffffffu) : ~e;
    return __uint_as_float(u);
}
__device__ __forceinline__ int load_index(const void* p, long i, bool is64) {
    if (is64) return (int)((const long long*)p)[i];
    return ((const int*)p)[i];
}

// packed f32x2 helpers (Blackwell FFMA2 — PTX-only)
#define FMA_F32X2(d, a, b, c) \
    asm("fma.rn.f32x2 %0, %1, %2, %3;" : "=l"(d) : "l"(a), "l"(b), "l"(c))
#define PACKF2(out, lo, hi) \
    asm("mov.b64 %0, {%1, %2};" : "=l"(out) : "f"(lo), "f"(hi))
#define UNPACKF2(lo, hi, in) \
    asm("mov.b64 {%0, %1}, %2;" : "=f"(lo), "=f"(hi) : "l"(in))

// block-wide inclusive scan (int), 256 threads
__device__ __forceinline__ int block_incl_scan(int v, int tid, int* wsum) {
#pragma unroll
    for (int o = 1; o < 32; o <<= 1) {
        int nv = __shfl_up_sync(0xffffffffu, v, o);
        if ((tid & 31) >= o) v += nv;
    }
    if ((tid & 31) == 31) wsum[tid >> 5] = v;
    __syncthreads();
    if (tid < 8) {
        int w = wsum[tid];
#pragma unroll
        for (int o = 1; o < 8; o <<= 1) {
            int nv = __shfl_up_sync(0xffu, w, o);
            if (tid >= o) w += nv;
        }
        wsum[tid] = w;
    }
    __syncthreads();
    if (tid >= 32) v += wsum[(tid >> 5) - 1];
    return v;
}

// ---------------- kernels ----------------

// zero x_new region, zero deg, init scalars, detect index dtype.
__global__ void __launch_bounds__(256) k_init(float* __restrict__ out,
                                              const void* __restrict__ eidx) {
    long i = (long)blockIdx.x * blockDim.x + threadIdx.x;   // 1.6M exact
    ((float4*)out)[i] = make_float4(0.f, 0.f, 0.f, 0.f);
    if (i == 0) { g_maxenc = 0u; g_sum = 0.f; }
    if (i < N_NODES) g_deg[i] = 0;
    // dtype detect: odd 32-bit words of first N_EDGES pairs are 0 iff int64.
    // (int32 buffer has 2*N_EDGES words, so reads stay in-bounds either way.)
    if (i < N_EDGES) {
        unsigned v = ((const unsigned*)eidx)[2 * i + 1];
        if (__any_sync(0xffffffffu, v != 0u) && ((threadIdx.x & 31) == 0))
            atomicOr(&g_or32, 1u);   // monotone: never reset (race-free)
    }
}

// Wh = x @ W  (50000x256x128), FFMA2 inner loop, fused s_src/s_tgt epilogue.
// 128x128 tile, TK=32, 256 threads, 8x8 per thread, acc packed over row pairs.
__global__ void __launch_bounds__(256) k_gemm(const float* __restrict__ x,
                                              const float* __restrict__ W,
                                              const float* __restrict__ a) {
    __shared__ float xs[128][36];      // [row][k], padded
    __shared__ float ws[32][128];      // [k][col]
    int tid = threadIdx.x;
    int tx = tid & 15;                 // cols tx*8..+7
    int ty = tid >> 4;                 // rows ty*8..+7
    int row0 = blockIdx.x * 128;

    unsigned long long acc[4][8];      // [row-pair][col], f32x2
#pragma unroll
    for (int i = 0; i < 4; i++)
#pragma unroll
        for (int j = 0; j < 8; j++) acc[i][j] = 0ull;

    for (int k0 = 0; k0 < IN_DIM; k0 += 32) {
#pragma unroll
        for (int r = 0; r < 4; r++) {           // x tile: 128x32
            int m = tid + 256 * r;
            int rr = m >> 3, c4 = m & 7;
            int grow = row0 + rr;
            float4 v = make_float4(0.f, 0.f, 0.f, 0.f);
            if (grow < N_NODES)
                v = *(const float4*)(x + (long)grow * IN_DIM + k0 + c4 * 4);
            *(float4*)&xs[rr][c4 * 4] = v;
        }
#pragma unroll
        for (int r = 0; r < 4; r++) {           // W tile: 32x128
            int m = tid + 256 * r;
            int kk = m >> 5, c4 = m & 31;
            *(float4*)&ws[kk][c4 * 4] =
                *(const float4*)(W + (long)(k0 + kk) * OUT_DIM + c4 * 4);
        }
        __syncthreads();
#pragma unroll
        for (int kq = 0; kq < 32; kq += 4) {
            float4 xv[8];
#pragma unroll
            for (int i = 0; i < 8; i++) xv[i] = *(float4*)&xs[ty * 8 + i][kq];
#pragma unroll
            for (int k2 = 0; k2 < 4; k2++) {
                float4 w0 = *(float4*)&ws[kq + k2][tx * 8];
                float4 w1 = *(float4*)&ws[kq + k2][tx * 8 + 4];
                float wa[8] = {w0.x, w0.y, w0.z, w0.w, w1.x, w1.y, w1.z, w1.w};
                unsigned long long wd[8];
#pragma unroll
                for (int j = 0; j < 8; j++) PACKF2(wd[j], wa[j], wa[j]);
#pragma unroll
                for (int ip = 0; ip < 4; ip++) {
                    float xa0[4] = {xv[2*ip].x,   xv[2*ip].y,   xv[2*ip].z,   xv[2*ip].w};
                    float xa1[4] = {xv[2*ip+1].x, xv[2*ip+1].y, xv[2*ip+1].z, xv[2*ip+1].w};
                    unsigned long long xp;
                    PACKF2(xp, xa0[k2], xa1[k2]);
#pragma unroll
                    for (int j = 0; j < 8; j++)
                        FMA_F32X2(acc[ip][j], xp, wd[j], acc[ip][j]);
                }
            }
        }
        __syncthreads();
    }

    // unpack to per-row values
    float rowv[8][8];
#pragma unroll
    for (int ip = 0; ip < 4; ip++)
#pragma unroll
        for (int j = 0; j < 8; j++) {
            float lo, hi;
            UNPACKF2(lo, hi, acc[ip][j]);
            rowv[2 * ip][j] = lo;
            rowv[2 * ip + 1][j] = hi;
        }

    float a1[8], a2[8];
#pragma unroll
    for (int j = 0; j < 8; j++) {
        a1[j] = a[tx * 8 + j];
        a2[j] = a[OUT_DIM + tx * 8 + j];
    }
#pragma unroll
    for (int i = 0; i < 8; i++) {
        int grow = row0 + ty * 8 + i;
        float p1 = 0.f, p2 = 0.f;
#pragma unroll
        for (int j = 0; j < 8; j++) {
            p1 += rowv[i][j] * a1[j];
            p2 += rowv[i][j] * a2[j];
        }
#pragma unroll
        for (int o = 1; o < 16; o <<= 1) {     // reduce over 16 tx lanes
            p1 += __shfl_xor_sync(0xffffffffu, p1, o);
            p2 += __shfl_xor_sync(0xffffffffu, p2, o);
        }
        if (grow < N_NODES) {
            *(float4*)(g_Wh + (long)grow * OUT_DIM + tx * 8) =
                make_float4(rowv[i][0], rowv[i][1], rowv[i][2], rowv[i][3]);
            *(float4*)(g_Wh + (long)grow * OUT_DIM + tx * 8 + 4) =
                make_float4(rowv[i][4], rowv[i][5], rowv[i][6], rowv[i][7]);
            if (tx == 0) { g_ssrc[grow] = p1; g_stgt[grow] = p2; }
        }
    }
}

// scores, int32 index conversion, in-degree histogram, global max
__global__ void __launch_bounds__(256) k_score(const void* __restrict__ eidx) {
    int e = blockIdx.x * blockDim.x + threadIdx.x;   // exact grid
    bool is64 = (g_or32 == 0u);
    int s = load_index(eidx, e, is64);
    int t = load_index(eidx, (long)N_EDGES + e, is64);
    g_src32[e] = s;
    g_tgt32[e] = t;
    atomicAdd(&g_deg[t], 1);
    float sc = __ldg(g_ssrc + s) + __ldg(g_stgt + t);
    sc = sc > 0.f ? sc : 0.2f * sc;                  // leaky_relu 0.2
    g_scores[e] = sc;

    float m = sc;
#pragma unroll
    for (int o = 16; o > 0; o >>= 1) m = fmaxf(m, __shfl_xor_sync(0xffffffffu, m, o));
    __shared__ float red[8];
    int wid = threadIdx.x >> 5;
    if ((threadIdx.x & 31) == 0) red[wid] = m;
    __syncthreads();
    if (threadIdx.x == 0) {
        float bm = red[0];
#pragma unroll
        for (int i = 1; i < 8; i++) bm = fmaxf(bm, red[i]);
        atomicMax(&g_maxenc, encf(bm));
    }
}

// 3-phase exclusive scan of g_deg -> g_off / g_cursor
__global__ void __launch_bounds__(256) k_scan1() {
    __shared__ int wsum[8];
    int i = blockIdx.x * 256 + threadIdx.x;
    int v = (i < N_NODES) ? g_deg[i] : 0;
    int incl = block_incl_scan(v, threadIdx.x, wsum);
    if (i < N_NODES) g_scanv[i] = incl;
    if (threadIdx.x == 255) g_bsum[blockIdx.x] = incl;
}
__global__ void __launch_bounds__(256) k_scan2() {
    __shared__ int wsum[8];
    int b = threadIdx.x;
    int v = (b < NB_SCAN) ? g_bsum[b] : 0;
    int incl = block_incl_scan(v, b, wsum);
    if (b < NB_SCAN) g_boff[b] = incl - v;          // exclusive
}
__global__ void __launch_bounds__(256) k_scan3() {
    int i = blockIdx.x * 256 + threadIdx.x;
    if (i < N_NODES) {
        int off = g_scanv[i] - g_deg[i] + g_boff[i >> 8];
        g_off[i] = off;
        g_cursor[i] = off;
    }
}

// CSR fill + softmax denominator (replaces k_sumexp)
__global__ void __launch_bounds__(256) k_fill() {
    int e = blockIdx.x * blockDim.x + threadIdx.x;   // exact grid
    float gmax = decf(g_maxenc);
    int t = g_tgt32[e];
    float z = expf(g_scores[e] - gmax);
    int pos = atomicAdd(&g_cursor[t], 1);
    g_csrc[pos] = g_src32[e];
    g_cz[pos] = z;

    float zs = z;
#pragma unroll
    for (int o = 16; o > 0; o >>= 1) zs += __shfl_xor_sync(0xffffffffu, zs, o);
    __shared__ float red[8];
    int wid = threadIdx.x >> 5;
    if ((threadIdx.x & 31) == 0) red[wid] = zs;
    __syncthreads();
    if (threadIdx.x == 0) {
        float bs = 0.f;
#pragma unroll
        for (int i = 0; i < 8; i++) bs += red[i];
        atomicAdd(&g_sum, bs);
    }
}

// gather: x_new[n] = inv_sum * sum_e z_e * Wh[src_e].  Warp per node, no atomics.
__global__ void __launch_bounds__(256) k_gather(float* __restrict__ xnew) {
    int n = (blockIdx.x * 256 + threadIdx.x) >> 5;   // 50000 exact
    int lane = threadIdx.x & 31;
    int start = g_off[n];
    int cnt = g_deg[n];
    float inv = 1.f / g_sum;
    float4 acc = make_float4(0.f, 0.f, 0.f, 0.f);
    int j = 0;
    for (; j + 2 <= cnt; j += 2) {
        int   s0 = g_csrc[start + j];
        int   s1 = g_csrc[start + j + 1];
        float z0 = g_cz[start + j];
        float z1 = g_cz[start + j + 1];
        float4 v0 = *(const float4*)(g_Wh + (long)s0 * OUT_DIM + lane * 4);
        float4 v1 = *(const float4*)(g_Wh + (long)s1 * OUT_DIM + lane * 4);
        acc.x = fmaf(z0, v0.x, acc.x); acc.y = fmaf(z0, v0.y, acc.y);
        acc.z = fmaf(z0, v0.z, acc.z); acc.w = fmaf(z0, v0.w, acc.w);
        acc.x = fmaf(z1, v1.x, acc.x); acc.y = fmaf(z1, v1.y, acc.y);
        acc.z = fmaf(z1, v1.z, acc.z); acc.w = fmaf(z1, v1.w, acc.w);
    }
    if (j < cnt) {
        int   s0 = g_csrc[start + j];
        float z0 = g_cz[start + j];
        float4 v0 = *(const float4*)(g_Wh + (long)s0 * OUT_DIM + lane * 4);
        acc.x = fmaf(z0, v0.x, acc.x); acc.y = fmaf(z0, v0.y, acc.y);
        acc.z = fmaf(z0, v0.z, acc.z); acc.w = fmaf(z0, v0.w, acc.w);
    }
    acc.x *= inv; acc.y *= inv; acc.z *= inv; acc.w *= inv;
    *(float4*)(xnew + (long)n * OUT_DIM + lane * 4) = acc;
}

// MLP head: h = relu(x_new@W1+b1); evidence = softplus(h@W2+b2)+1
__global__ void __launch_bounds__(64) k_mlp(const float* __restrict__ xnew,
                                            const float* __restrict__ W1,
                                            const float* __restrict__ b1,
                                            const float* __restrict__ W2,
                                            const float* __restrict__ b2,
                                            float* __restrict__ ev) {
    __shared__ float W1s[OUT_DIM * HID];
    __shared__ float xs[OUT_DIM][16];
    __shared__ float hs[16 * 65];
    __shared__ float W2s[HID * NCLS];
    __shared__ float b2s[NCLS];

    int tid = threadIdx.x;
    for (int i = tid; i < OUT_DIM * HID / 4; i += 64)
        ((float4*)W1s)[i] = ((const float4*)W1)[i];
    for (int i = tid; i < HID * NCLS; i += 64) W2s[i] = W2[i];
    if (tid < NCLS) b2s[tid] = b2[tid];
    float bb = b1[tid];

    int n0 = blockIdx.x * 16;
    for (int i = tid; i < 512; i += 64) {
        int c4 = i >> 4, n = i & 15;
        float4 v = *(const float4*)(xnew + (long)(n0 + n) * OUT_DIM + c4 * 4);
        xs[c4 * 4 + 0][n] = v.x;
        xs[c4 * 4 + 1][n] = v.y;
        xs[c4 * 4 + 2][n] = v.z;
        xs[c4 * 4 + 3][n] = v.w;
    }
    __syncthreads();

    float acc[16];
#pragma unroll
    for (int n = 0; n < 16; n++) acc[n] = bb;
    for (int k = 0; k < OUT_DIM; k++) {
        float wv = W1s[k * HID + tid];
        float4 x0 = *(float4*)&xs[k][0];
        float4 x1 = *(float4*)&xs[k][4];
        float4 x2 = *(float4*)&xs[k][8];
        float4 x3 = *(float4*)&xs[k][12];
        acc[0]  += wv * x0.x; acc[1]  += wv * x0.y; acc[2]  += wv * x0.z; acc[3]  += wv * x0.w;
        acc[4]  += wv * x1.x; acc[5]  += wv * x1.y; acc[6]  += wv * x1.z; acc[7]  += wv * x1.w;
        acc[8]  += wv * x2.x; acc[9]  += wv * x2.y; acc[10] += wv * x2.z; acc[11] += wv * x2.w;
        acc[12] += wv * x3.x; acc[13] += wv * x3.y; acc[14] += wv * x3.z; acc[15] += wv * x3.w;
    }
#pragma unroll
    for (int n = 0; n < 16; n++) hs[n * 65 + tid] = fmaxf(acc[n], 0.f);
    __syncthreads();

    if (tid < 16 * NCLS) {
        int n = tid / NCLS, j = tid % NCLS;
        float z = b2s[j];
        for (int k = 0; k < HID; k++) z += hs[n * 65 + k] * W2s[k * NCLS + j];
        float sp = (z > 20.f) ? z : log1pf(expf(z));
        ev[(long)(n0 + n) * NCLS + j] = sp + 1.f;
    }
}

// ---------------- launch ----------------
extern "C" void kernel_launch(void* const* d_in, const int* in_sizes, int n_in,
                              void* d_out, int out_size) {
    const float* x  = (const float*)d_in[0];
    const void*  ei = d_in[1];
    const float* W  = (const float*)d_in[2];
    const float* a  = (const float*)d_in[3];
    const float* W1 = (const float*)d_in[4];
    const float* b1 = (const float*)d_in[5];
    const float* W2 = (const float*)d_in[6];
    const float* b2 = (const float*)d_in[7];
    float* out = (float*)d_out;
    float* ev  = out + (long)N_NODES * OUT_DIM;

    k_init  <<<(N_NODES * OUT_DIM / 4) / 256, 256>>>(out, ei); // 6250
    k_gemm  <<<(N_NODES + 127) / 128, 256>>>(x, W, a);         // 391
    k_score <<<N_EDGES / 256, 256>>>(ei);                      // 3125
    k_scan1 <<<NB_SCAN, 256>>>();                              // 196
    k_scan2 <<<1, 256>>>();
    k_scan3 <<<NB_SCAN, 256>>>();                              // 196
    k_fill  <<<N_EDGES / 256, 256>>>();                        // 3125
    k_gather<<<N_NODES * 32 / 256, 256>>>(out);                // 6250
    k_mlp   <<<N_NODES / 16, 64>>>(out, W1, b1, W2, b2, ev);   // 3125
}